// round 8
// baseline (speedup 1.0000x reference)
#include <cuda_runtime.h>
#include <cuda_bf16.h>

// SEIR RNN, two-phase checkpointed segment-parallel kernel.
//
// History: all single/low-occupancy variants pin at ~36us profiled with NO
// resource saturated (DRAM 50%, L2 49%, L1 58%, occ ~20%).  R7 proved
// warmup-recompute is wrong (critical path unchanged, 8x issue).  R4 proved
// checkpointing is numerically exact but its 53KB tiles capped occ at 21%.
// R8 = checkpoints + 22.5KB tiles -> phase2 at ~40 warps/SM, 3x store MLP,
// compute pipes idle.  Decisive test of the latency-x-MLP equilibrium model.

#define BATCH    65536
#define STEPS    200
#define SEGLEN   25
#define NSEG     8
#define TRAJ_W   4                  // trajectories per warp (phase 2)
#define TPB      128
#define WARPS    (TPB / 32)
#define TRAJ_BLK (WARPS * TRAJ_W)   // 16 trajectories per block (phase 2)
#define TSTRIDE  11                 // tile row stride in float4

__device__ float4 g_ckpt[NSEG * BATCH];   // 8 MB scratch, [seg][traj]

struct Coef { float kB, cA, cC, kA, kC; };

__device__ __forceinline__ Coef make_coef(const float* __restrict__ w)
{
    const float A = w[4], B = w[5], C = w[6], H = 0.5f;
    Coef c;
    c.kB = H * B * 1e-5f;     // H*B/N_POP
    c.cA = 1.0f - H * A;
    c.cC = 1.0f - H * C;
    c.kA = H * A;
    c.kC = H * C;
    return c;
}

__device__ __forceinline__ void step(const Coef& c, float& s, float& e,
                                     float& i, float& r)
{
    float p     = e + i;
    float inflH = c.kB * p * s;
    float eo = e, io = i;
    s = s - inflH;
    e = fmaf(c.cA, eo, inflH);
    i = fmaf(c.cC, io, c.kA * eo);
    r = fmaf(c.kC, io, r);
}

// ---------------- Phase 1: run full chain, store 8 checkpoints ------------
__global__ __launch_bounds__(TPB)
void seir_phase1(const float4* __restrict__ init, const float* __restrict__ w)
{
    const int j = blockIdx.x * TPB + threadIdx.x;
    const Coef c = make_coef(w);

    float4 x = init[j];
    float s = x.x, e = x.y, i = x.z, r = x.w;

    #pragma unroll 1
    for (int sg = 0; sg < NSEG; ++sg) {
        g_ckpt[sg * BATCH + j] = make_float4(s, e, i, r);  // coalesced
        #pragma unroll
        for (int t = 0; t < SEGLEN; ++t)
            step(c, s, e, i, r);
    }
}

// ---------------- Phase 2: 25 steps per lane, coalesced drain -------------
__global__ __launch_bounds__(TPB)
void seir_phase2(const float* __restrict__ w, float4* __restrict__ out)
{
    __shared__ float4 tile[WARPS][32][TSTRIDE];   // 22528 B

    const int tid  = threadIdx.x;
    const int wrp  = tid >> 5;
    const int lane = tid & 31;
    const int tl   = lane >> 3;          // trajectory within warp (0..3)
    const int sg   = lane & 7;           // segment (0..7)
    const int trajBase = blockIdx.x * TRAJ_BLK + wrp * TRAJ_W;

    const Coef c = make_coef(w);

    float4 x = g_ckpt[sg * BATCH + trajBase + tl];
    float s = x.x, e = x.y, i = x.z, r = x.w;

    float4* const out_traj = out + (size_t)trajBase * STEPS;

    #pragma unroll
    for (int rnd = 0; rnd < 3; ++rnd) {
        const int cstart = rnd * 8;
        const int len    = (rnd == 2) ? 9 : 8;

        for (int tt = 0; tt < len; ++tt) {
            step(c, s, e, i, r);
            tile[wrp][lane][tt] = make_float4(s, e, i, r);
        }
        __syncwarp();

        // iter m: 32 lanes cover tile rows m*4..m*4+3 x steps 0..7
        // -> 4 full 128B lines per STG pass.
        #pragma unroll
        for (int m = 0; m < 8; ++m) {
            int row = m * 4 + (lane >> 3);
            int st  = lane & 7;
            int rtl = row >> 3;                    // trajectory
            int rsg = row & 7;                     // segment
            out_traj[(size_t)rtl * STEPS + rsg * SEGLEN + cstart + st] =
                tile[wrp][row][st];
        }
        if (len == 9) {
            // leftover step 24 of each segment: one float4 per lane
            out_traj[(size_t)(lane >> 3) * STEPS + (lane & 7) * SEGLEN + 24] =
                tile[wrp][lane][8];
        }
        __syncwarp();
    }
}

extern "C" void kernel_launch(void* const* d_in, const int* in_sizes, int n_in,
                              void* d_out, int out_size)
{
    const float4* init = (const float4*)d_in[0];   // (65536,1,4) f32
    const float*  wts  = (const float*)d_in[1];    // (7,) f32
    float4*       out  = (float4*)d_out;           // (65536,200,1,4) f32

    seir_phase1<<<BATCH / TPB, TPB>>>(init, wts);
    seir_phase2<<<BATCH / TRAJ_BLK, TPB>>>(wts, out);
}

// round 9
// speedup vs baseline: 1.6123x; 1.6123x over previous
#include <cuda_runtime.h>
#include <cuda_bf16.h>

// SEIR RNN. Conclusion from R1-R8: E2E period (41.5us) is invariant to
// kernel-side time (35.7-37.2us across 5 variants) => steady-state graph
// replay is gated by draining the 210MB output to DRAM at ~5.06 TB/s.
// SM-side structure, store contiguity, occupancy, and L2 eviction policies
// are all proven neutral.  This round tests the last lever: write-through
// stores (st.global.wt) eliminate L2 dirty-line churn from the write path.
// Structure otherwise identical to the best kernel (R1, 41.472us).

#define BATCH   65536
#define STEPS   200
#define CHUNK   8
#define NCHUNK  (STEPS / CHUNK)   // 25
#define TPB     128
#define WARPS   (TPB / 32)

__device__ __forceinline__ void st_wt(float4* p, float4 v)
{
    asm volatile("st.global.wt.v4.f32 [%0], {%1,%2,%3,%4};"
                 :: "l"(p), "f"(v.x), "f"(v.y), "f"(v.z), "f"(v.w)
                 : "memory");
}

__global__ __launch_bounds__(TPB, 8)
void seir_kernel(const float4* __restrict__ init,
                 const float*  __restrict__ w,
                 float4*       __restrict__ out)
{
    // Warp-private staging tile, +1 float4 row pad (stride 144 B,
    // conflict-free for both the per-step STS and the transposed LDS drain).
    __shared__ float4 buf[2][WARPS][32][CHUNK + 1];

    const int tid  = threadIdx.x;
    const int wrp  = tid >> 5;
    const int lane = tid & 31;
    const int bw   = blockIdx.x * TPB + wrp * 32;   // first trajectory of warp
    const int b    = bw + lane;

    const float A = w[4];
    const float B = w[5];
    const float C = w[6];
    const float H = 0.5f;
    const float kB = H * B * 1e-5f;   // H*B/N_POP
    const float cA = 1.0f - H * A;
    const float cC = 1.0f - H * C;
    const float kA = H * A;
    const float kC = H * C;

    float4 x = init[b];
    float s = x.x, e = x.y, i = x.z, r = x.w;

    // lane-constant drain indices
    const int bl = lane >> 3;         // 0..3 : trajectory sub-index per k
    const int t  = lane & 7;          // 0..7 : step within chunk
    float4* const out_base = out + (size_t)(bw) * STEPS + t;

    for (int c = 0; c < NCHUNK; ++c) {
        const int pb = c & 1;
        // ---- compute 8 steps, stage in warp-private shared tile ----
        #pragma unroll
        for (int tt = 0; tt < CHUNK; ++tt) {
            float p     = e + i;
            float inflH = kB * p * s;
            float eo = e, io = i;
            s = s - inflH;
            e = fmaf(cA, eo, inflH);
            i = fmaf(cC, io, kA * eo);
            r = fmaf(kC, io, r);
            buf[pb][wrp][lane][tt] = make_float4(s, e, i, r);
        }
        __syncwarp();

        // ---- coalesced drain: per k, 8 lanes = one full 128 B line;
        //      write-through => no L2 dirty-line residency/churn ----
        const int tbase = c * CHUNK;
        #pragma unroll
        for (int k = 0; k < CHUNK; ++k) {
            int bl_k = 4 * k + bl;
            st_wt(&out_base[(size_t)bl_k * STEPS + tbase],
                  buf[pb][wrp][bl_k][t]);
        }
        // no trailing sync: next chunk uses the other buffer
    }
}

extern "C" void kernel_launch(void* const* d_in, const int* in_sizes, int n_in,
                              void* d_out, int out_size)
{
    const float4* init = (const float4*)d_in[0];   // (65536,1,4) f32
    const float*  wts  = (const float*)d_in[1];    // (7,) f32
    float4*       out  = (float4*)d_out;           // (65536,200,1,4) f32

    seir_kernel<<<BATCH / TPB, TPB>>>(init, wts, out);
}